// round 9
// baseline (speedup 1.0000x reference)
#include <cuda_runtime.h>
#include <cuda_fp16.h>
#include <math.h>
#include <stdint.h>

#define NHALF 8192
#define NTOT  16384
#define DIMK  128
#define NAB   4096
#define NTRI  2080
#define NTILES (NAB + 2 * NTRI)   // 8256
#define NCTAS  296                // 148 SMs x 2
#define SLOTB  32768u             // stage: A-half 16KB + B-half 16KB

// ---------------- device scratch ----------------
__device__ float g_norm[NTOT];
__device__ float g_rowsum_aa[NHALF];
__device__ float g_rowsum_bb[NHALF];
__device__ float g_rowsum_ab[NHALF];
__device__ float g_colsum_ab[NHALF];
__device__ float g_alignneg;
__device__ float g_alignpart[1024];
__device__ float g_logsum;
__device__ unsigned int g_finctr;
__device__ __half g_h[(size_t)NTOT * DIMK];

__device__ __forceinline__ uint32_t s2u(const void* p) {
    uint32_t r;
    asm("{ .reg .u64 t; cvta.to.shared.u64 t, %1; cvt.u32.u64 %0, t; }"
        : "=r"(r) : "l"(p));
    return r;
}

__device__ __forceinline__ void mma_f16acc(uint32_t* d, const uint32_t* a, const uint32_t* b) {
    asm volatile(
        "mma.sync.aligned.m16n8k16.row.col.f16.f16.f16.f16 "
        "{%0,%1}, {%2,%3,%4,%5}, {%6,%7}, {%0,%1};"
        : "+r"(d[0]), "+r"(d[1])
        : "r"(a[0]), "r"(a[1]), "r"(a[2]), "r"(a[3]), "r"(b[0]), "r"(b[1]));
}

#define LDSM_X4(r0, r1, r2, r3, addr) \
    asm volatile("ldmatrix.sync.aligned.m8n8.x4.shared.b16 {%0,%1,%2,%3}, [%4];" \
                 : "=r"(r0), "=r"(r1), "=r"(r2), "=r"(r3) : "r"(addr))

__device__ __forceinline__ float frcp(float x) {
    float r;
    asm("rcp.approx.f32 %0, %1;" : "=f"(r) : "f"(x));
    return r;
}

// tile id -> (q, ti, tj). id<NAB: ab. Then aa, bb upper triangles.
__device__ __forceinline__ void decode_tile(int id, int& q, int& ti, int& tj) {
    if (id < NAB) { q = 2; ti = id >> 6; tj = id & 63; return; }
    int t = id - NAB;
    q = (t < NTRI) ? 0 : 1;
    int u = q ? (t - NTRI) : t;
    int up = (NTRI - 1) - u;
    int r = (int)((sqrtf(8.f * up + 1.f) - 1.f) * 0.5f);
    while ((r + 1) * (r + 2) / 2 <= up) r++;
    while (r * (r + 1) / 2 > up) r--;
    ti = 63 - r;
    tj = 63 - (up - r * (r + 1) / 2);
}

// ---------------- fused setup ----------------
__global__ void setup_kernel(const float* __restrict__ F) {
    const int b = blockIdx.x;
    const int tid = threadIdx.x;
    const int wid = tid >> 5, lane = tid & 31;

    if (b < 2048) {
        int gw = b * 8 + wid;
        float4 v = reinterpret_cast<const float4*>(F + (size_t)gw * DIMK)[lane];
        __half2 h0 = __floats2half2_rn(v.x, v.y);
        __half2 h1 = __floats2half2_rn(v.z, v.w);
        __half2* dst = reinterpret_cast<__half2*>(g_h + (size_t)gw * DIMK);
        dst[lane * 2 + 0] = h0;
        dst[lane * 2 + 1] = h1;
        float2 c0 = __half22float2(h0), c1 = __half22float2(h1);
        float s = c0.x * c0.x + c0.y * c0.y + c1.x * c1.x + c1.y * c1.y;
        #pragma unroll
        for (int o = 16; o > 0; o >>= 1) s += __shfl_xor_sync(0xffffffffu, s, o);
        if (lane == 0) g_norm[gw] = s;
    } else if (b < 3072) {
        __shared__ float sh[8];
        int gw = (b - 2048) * 8 + wid;
        float4 a = reinterpret_cast<const float4*>(F + (size_t)gw * DIMK)[lane];
        float4 bb = reinterpret_cast<const float4*>(F + (size_t)(gw + NHALF) * DIMK)[lane];
        float dx = a.x - bb.x, dy = a.y - bb.y, dz = a.z - bb.z, dw = a.w - bb.w;
        float s = dx * dx + dy * dy + dz * dz + dw * dw;
        #pragma unroll
        for (int o = 16; o > 0; o >>= 1) s += __shfl_xor_sync(0xffffffffu, s, o);
        if (lane == 0) sh[wid] = logf(1.f + s);
        __syncthreads();
        if (tid == 0) {
            float t = 0.f;
            #pragma unroll
            for (int i = 0; i < 8; i++) t += sh[i];
            g_alignpart[b - 2048] = t;
        }
    } else {
        int i = (b - 3072) * 256 + tid;
        if (i < NHALF) {
            g_rowsum_aa[i] = 0.f; g_rowsum_bb[i] = 0.f;
            g_rowsum_ab[i] = 0.f; g_colsum_ab[i] = 0.f;
        }
        if (i == 0) { g_alignneg = 0.f; g_logsum = 0.f; g_finctr = 0u; }
    }
}

// ---------------- stage load: (tile, khalf) -> slot ----------------
__device__ __forceinline__ void issue_stage(int tile, int khalf, uint32_t slotBase, int tid) {
    int q, ti, tj;
    decode_tile(tile, q, ti, tj);
    int iB = ((q == 1) ? NHALF : 0) + ti * 128;
    int jB = ((q == 0) ? 0 : NHALF) + tj * 128;
    #pragma unroll
    for (int it = 0; it < 8; it++) {
        int c = tid + it * 256;              // 0..2047
        bool isA = c < 1024;
        int r = (c & 1023) >> 3;
        int kc = c & 7;
        const __half* gp = g_h + (size_t)((isA ? iB : jB) + r) * DIMK + khalf * 64 + kc * 8;
        uint32_t dst = slotBase + (isA ? 0u : 16384u) + r * 128 + ((kc ^ (r & 7)) << 4);
        asm volatile("cp.async.cg.shared.global [%0], [%1], 16;" :: "r"(dst), "l"(gp));
    }
    asm volatile("cp.async.commit_group;" ::: "memory");
}

// ---------------- persistent pair kernel ----------------
__global__ void __launch_bounds__(256, 2) pair_persist_kernel() {
    extern __shared__ char sm[];
    __shared__ float rowAcc[128][4];
    __shared__ float colAcc[128][2];

    const int tid = threadIdx.x;
    const int wid = tid >> 5, lane = tid & 31;
    const int g = lane >> 2, t4 = lane & 3;
    const int rowOff = (wid >> 2) * 64;
    const int colOff = (wid & 3) * 32;
    const uint32_t smbase = s2u(sm);
    const int bid = blockIdx.x;

    const int ntloc = (NTILES - 1 - bid) / NCTAS + 1;
    const int T = 2 * ntloc;

    // ldmatrix invariant addressing
    uint32_t aTerm[4]; int rsA[4];
    uint32_t bTerm[2]; int rsB[2];
    const int kbA = lane >> 4;
    const int kbB = (lane >> 3) & 1;
    #pragma unroll
    for (int mt = 0; mt < 4; mt++) {
        int row = rowOff + mt * 16 + (lane & 7) + ((lane >> 3) & 1) * 8;
        aTerm[mt] = row * 128;
        rsA[mt] = row & 7;
    }
    #pragma unroll
    for (int bt = 0; bt < 2; bt++) {
        int nrow = colOff + bt * 16 + ((lane >> 4) * 8) + (lane & 7);
        bTerm[bt] = 16384u + nrow * 128;
        rsB[bt] = nrow & 7;
    }

    // prologue: fill the 3-slot ring
    #pragma unroll
    for (int s = 0; s < 3; s++)
        if (s < T)
            issue_stage(bid + (s >> 1) * NCTAS, s & 1, smbase + (uint32_t)(s % 3) * SLOTB, tid);

    uint32_t acc[4][4][2];
    float rnF[8], cnF[8];
    int q = 0, ti = 0, tj = 0;
    bool dz = false;

    for (int s = 0; s < T; s++) {
        const int rem = T - 1 - s;
        if (rem >= 2)      asm volatile("cp.async.wait_group 2;" ::: "memory");
        else if (rem == 1) asm volatile("cp.async.wait_group 1;" ::: "memory");
        else               asm volatile("cp.async.wait_group 0;" ::: "memory");
        __syncthreads();

        const uint32_t slot = smbase + (uint32_t)(s % 3) * SLOTB;
        const int khalf = s & 1;

        if (khalf == 0) {
            decode_tile(bid + (s >> 1) * NCTAS, q, ti, tj);
            dz = (q < 2) && (ti == tj);
            int iB = ((q == 1) ? NHALF : 0) + ti * 128;
            int jB = ((q == 0) ? 0 : NHALF) + tj * 128;
            #pragma unroll
            for (int k = 0; k < 8; k++) {
                rnF[k] = __ldg(&g_norm[iB + rowOff + (k >> 1) * 16 + g + (k & 1) * 8]);
                cnF[k] = __ldg(&g_norm[jB + colOff + (k >> 1) * 8 + 2 * t4 + (k & 1)]) + 1.f;
            }
            #pragma unroll
            for (int mt = 0; mt < 4; mt++)
                #pragma unroll
                for (int nt = 0; nt < 4; nt++) { acc[mt][nt][0] = 0u; acc[mt][nt][1] = 0u; }
        }

        // MMA: 4 local ksteps on this stage
        #pragma unroll
        for (int ksl = 0; ksl < 4; ksl++) {
            uint32_t af[4][4], bf[4][2];
            #pragma unroll
            for (int mt = 0; mt < 4; mt++) {
                uint32_t addr = slot + aTerm[mt] + ((((2 * ksl + kbA) ^ rsA[mt])) << 4);
                LDSM_X4(af[mt][0], af[mt][1], af[mt][2], af[mt][3], addr);
            }
            #pragma unroll
            for (int bt = 0; bt < 2; bt++) {
                uint32_t addr = slot + bTerm[bt] + ((((2 * ksl + kbB) ^ rsB[bt])) << 4);
                LDSM_X4(bf[bt * 2][0], bf[bt * 2][1], bf[bt * 2 + 1][0], bf[bt * 2 + 1][1], addr);
            }
            #pragma unroll
            for (int mt = 0; mt < 4; mt++)
                #pragma unroll
                for (int nt = 0; nt < 4; nt++)
                    mma_f16acc(acc[mt][nt], af[mt], bf[nt]);
        }

        if (khalf == 1) {
            // ---- epilogue compute + staging ----
            float rowp[8];
            __half2 colh[4];
            #pragma unroll
            for (int i = 0; i < 8; i++) rowp[i] = 0.f;
            #pragma unroll
            for (int i = 0; i < 4; i++) colh[i] = __float2half2_rn(0.f);

            if (!dz) {
                const __half2 m2 = __float2half2_rn(-2.f);
                __half2 rn2[8], cn2[4];
                #pragma unroll
                for (int k = 0; k < 8; k++) rn2[k] = __float2half2_rn(rnF[k]);
                #pragma unroll
                for (int nt = 0; nt < 4; nt++)
                    cn2[nt] = __floats2half2_rn(cnF[2 * nt], cnF[2 * nt + 1]);
                #pragma unroll
                for (int mt = 0; mt < 4; mt++) {
                    __half2 rh0 = __float2half2_rn(0.f), rh1 = __float2half2_rn(0.f);
                    #pragma unroll
                    for (int nt = 0; nt < 4; nt++) {
                        __half2 a0 = *reinterpret_cast<__half2*>(&acc[mt][nt][0]);
                        __half2 a1 = *reinterpret_cast<__half2*>(&acc[mt][nt][1]);
                        __half2 s0 = h2rcp(__hfma2(a0, m2, __hadd2(rn2[2 * mt], cn2[nt])));
                        __half2 s1 = h2rcp(__hfma2(a1, m2, __hadd2(rn2[2 * mt + 1], cn2[nt])));
                        rh0 = __hadd2(rh0, s0);
                        rh1 = __hadd2(rh1, s1);
                        colh[nt] = __hadd2(colh[nt], __hadd2(s0, s1));
                    }
                    rowp[2 * mt]     = __low2float(rh0) + __high2float(rh0);
                    rowp[2 * mt + 1] = __low2float(rh1) + __high2float(rh1);
                }
            } else {
                // exact f32 path, diagonal zeroed; cols skipped (would double count)
                #pragma unroll
                for (int mt = 0; mt < 4; mt++)
                    #pragma unroll
                    for (int nt = 0; nt < 4; nt++)
                        #pragma unroll
                        for (int h = 0; h < 2; h++) {
                            float2 a2 = __half22float2(*reinterpret_cast<__half2*>(&acc[mt][nt][h]));
                            float rni = rnF[2 * mt + h];
                            int lrow = rowOff + mt * 16 + g + h * 8;
                            int lcol = colOff + nt * 8 + 2 * t4;
                            float s0 = frcp(fmaf(-2.f, a2.x, rni + cnF[2 * nt]));
                            float s1 = frcp(fmaf(-2.f, a2.y, rni + cnF[2 * nt + 1]));
                            if (lcol == lrow) s0 = 0.f;
                            if (lcol + 1 == lrow) s1 = 0.f;
                            rowp[2 * mt + h] += s0 + s1;
                        }
            }

            // rows: reduce over t4
            #pragma unroll
            for (int i = 0; i < 8; i++) {
                rowp[i] += __shfl_xor_sync(0xffffffffu, rowp[i], 1);
                rowp[i] += __shfl_xor_sync(0xffffffffu, rowp[i], 2);
            }
            if (t4 == 0) {
                #pragma unroll
                for (int mt = 0; mt < 4; mt++) {
                    rowAcc[rowOff + mt * 16 + g][wid & 3]     = rowp[2 * mt + 0];
                    rowAcc[rowOff + mt * 16 + g + 8][wid & 3] = rowp[2 * mt + 1];
                }
            }
            // cols: reduce half2 over g
            if (!dz) {
                #pragma unroll
                for (int nt = 0; nt < 4; nt++) {
                    colh[nt] = __hadd2(colh[nt], __shfl_xor_sync(0xffffffffu, colh[nt], 4));
                    colh[nt] = __hadd2(colh[nt], __shfl_xor_sync(0xffffffffu, colh[nt], 8));
                    colh[nt] = __hadd2(colh[nt], __shfl_xor_sync(0xffffffffu, colh[nt], 16));
                }
                if (g == 0) {
                    #pragma unroll
                    for (int nt = 0; nt < 4; nt++) {
                        colAcc[colOff + nt * 8 + 2 * t4][wid >> 2]     = __low2float(colh[nt]);
                        colAcc[colOff + nt * 8 + 2 * t4 + 1][wid >> 2] = __high2float(colh[nt]);
                    }
                }
            }
        }

        __syncthreads();   // slot free for reuse; staging visible

        if (khalf == 1) {
            if (tid < 128) {
                float v = rowAcc[tid][0] + rowAcc[tid][1] + rowAcc[tid][2] + rowAcc[tid][3];
                float* rdst = (q == 0) ? g_rowsum_aa : ((q == 1) ? g_rowsum_bb : g_rowsum_ab);
                atomicAdd(&rdst[ti * 128 + tid], v);
            } else if (!dz) {
                int c = tid - 128;
                float v = colAcc[c][0] + colAcc[c][1];
                if (q == 2) atomicAdd(&g_colsum_ab[tj * 128 + c], v);
                else        atomicAdd((q == 0) ? &g_rowsum_aa[tj * 128 + c]
                                               : &g_rowsum_bb[tj * 128 + c], v);
            }
        }

        const int s3 = s + 3;
        if (s3 < T)
            issue_stage(bid + (s3 >> 1) * NCTAS, s3 & 1,
                        smbase + (uint32_t)(s3 % 3) * SLOTB, tid);
    }
}

// ---------------- fused finalize ----------------
__global__ void finalize_kernel(float* __restrict__ out) {
    __shared__ bool isLast;
    int idx = blockIdx.x * 256 + threadIdx.x;
    float s = 0.f;
    for (int j = idx; j < NHALF; j += 4096) {
        s += logf(g_colsum_ab[j] + g_rowsum_bb[j]);
        s += logf(g_rowsum_aa[j] + g_rowsum_ab[j]);
    }
    #pragma unroll
    for (int o = 16; o > 0; o >>= 1) s += __shfl_xor_sync(0xffffffffu, s, o);
    if ((threadIdx.x & 31) == 0) atomicAdd(&g_logsum, s);

    if (blockIdx.x == 0) {
        float a = 0.f;
        for (int j = threadIdx.x; j < 1024; j += 256) a += g_alignpart[j];
        #pragma unroll
        for (int o = 16; o > 0; o >>= 1) a += __shfl_xor_sync(0xffffffffu, a, o);
        if ((threadIdx.x & 31) == 0) atomicAdd(&g_alignneg, a);
    }

    __threadfence();
    __syncthreads();
    if (threadIdx.x == 0) isLast = (atomicAdd(&g_finctr, 1u) == 15u);
    __syncthreads();
    if (isLast && threadIdx.x == 0)
        out[0] = g_alignneg / (float)NHALF + 0.5f * g_logsum / (float)NHALF;
}

// ---------------- launch ----------------
extern "C" void kernel_launch(void* const* d_in, const int* in_sizes, int n_in,
                              void* d_out, int out_size) {
    const float* F = (const float*)d_in[0];
    float* out = (float*)d_out;

    const int SMEM_BYTES = 3 * (int)SLOTB;   // 96 KB ring
    cudaFuncSetAttribute(pair_persist_kernel,
                         cudaFuncAttributeMaxDynamicSharedMemorySize, SMEM_BYTES);

    setup_kernel<<<3104, 256>>>(F);
    pair_persist_kernel<<<NCTAS, 256, SMEM_BYTES>>>();
    finalize_kernel<<<16, 256>>>(out);
}